// round 11
// baseline (speedup 1.0000x reference)
#include <cuda_runtime.h>
#include <cuda_fp16.h>
#include <math.h>
#include <stdint.h>

// Problem constants
#define BB 8
#define SS 1024
#define EE 768
#define HH 12
#define DD 64

// GEMM tiling
#define BM 128
#define BN 128
#define BK 64
#define LDH 72            // padded halves stride in smem tiles

// Attention smem stride (halves)
#define ATT_LDH 72

// q pre-scale: 1/sqrt(64) * log2(e)  (softmax runs in exp2 domain)
#define QSCALE (0.125f * 1.4426950408889634f)

// Scratch (allocation-free rule: __device__ globals)
__device__ __half g_xh[(size_t)BB * SS * EE];
__device__ __half g_wqkvh[(size_t)3 * EE * EE];
__device__ __half g_owh[(size_t)EE * EE];
__device__ __half g_qh[(size_t)BB * HH * SS * DD];
__device__ __half g_kh[(size_t)BB * HH * SS * DD];
__device__ __half g_vh[(size_t)BB * HH * SS * DD];
__device__ __half g_ctxh[(size_t)BB * SS * EE];
__device__ int    g_len[BB];

__device__ __forceinline__ uint32_t packh2(float a, float b) {
    __half2 h = __floats2half2_rn(a, b);
    return *(uint32_t*)&h;
}

#define MMA16816(C, A, B)                                                      \
    asm volatile("mma.sync.aligned.m16n8k16.row.col.f32.f16.f16.f32 "          \
        "{%0,%1,%2,%3}, {%4,%5,%6,%7}, {%8,%9}, {%0,%1,%2,%3};"                \
        : "+f"((C)[0]), "+f"((C)[1]), "+f"((C)[2]), "+f"((C)[3])               \
        : "r"((A)[0]), "r"((A)[1]), "r"((A)[2]), "r"((A)[3]),                  \
          "r"((B)[0]), "r"((B)[1]))

#define LDMATRIX_X4(R, ADDR)                                                   \
    asm volatile("ldmatrix.sync.aligned.m8n8.x4.shared.b16 {%0,%1,%2,%3}, [%4];" \
        : "=r"((R)[0]), "=r"((R)[1]), "=r"((R)[2]), "=r"((R)[3]) : "r"(ADDR))

#define LDMATRIX_X4_T(R, ADDR)                                                 \
    asm volatile("ldmatrix.sync.aligned.m8n8.x4.trans.shared.b16 {%0,%1,%2,%3}, [%4];" \
        : "=r"((R)[0]), "=r"((R)[1]), "=r"((R)[2]), "=r"((R)[3]) : "r"(ADDR))

// ---------------------------------------------------------------------------
// Fused fp32 -> fp16 conversion for x, Wqkv_w, out_w (one launch)
// ---------------------------------------------------------------------------
#define CN1 (BB * SS * EE / 4)
#define CN2 (3 * EE * EE / 4)
#define CN3 (EE * EE / 4)

__global__ void conv_all(const float* __restrict__ x, const float* __restrict__ w1,
                         const float* __restrict__ w2)
{
    int i = blockIdx.x * 256 + threadIdx.x;
    const float* src;
    __half* dst;
    if (i < CN1)              { src = x;  dst = g_xh; }
    else if (i < CN1 + CN2)   { src = w1; dst = g_wqkvh; i -= CN1; }
    else if (i < CN1+CN2+CN3) { src = w2; dst = g_owh;   i -= CN1 + CN2; }
    else return;
    const float4 v = ((const float4*)src)[i];
    ((__half2*)dst)[i * 2]     = __floats2half2_rn(v.x, v.y);
    ((__half2*)dst)[i * 2 + 1] = __floats2half2_rn(v.z, v.w);
}

// ---------------------------------------------------------------------------
// Mask -> per-batch valid length (prefix mask; count nonzeros).
// ---------------------------------------------------------------------------
__global__ void lengths_kernel(const unsigned char* __restrict__ mask)
{
    const int b = blockIdx.x;
    const int lane = threadIdx.x;
    int cnt = 0;
    if (mask[1] != 0) {
        const unsigned char* row = mask + (size_t)b * SS;
        for (int i = lane; i < SS; i += 32) cnt += (row[i] != 0);
    } else {
        const unsigned int* row = (const unsigned int*)mask + (size_t)b * SS;
        for (int i = lane; i < SS; i += 32) cnt += (row[i] != 0u);
    }
#pragma unroll
    for (int o = 16; o; o >>= 1) cnt += __shfl_xor_sync(0xffffffffu, cnt, o);
    if (lane == 0) g_len[b] = cnt;
}

// ---------------------------------------------------------------------------
// fp16 GEMM via raw mma.sync + ldmatrix.
// 3-stage cp.async ring, ONE __syncthreads per k-iteration, hoisted
// ldmatrix base addresses. CTA 128x128, BK=64, 8 warps (4m x 2n).
// MODE 0: scatter q/k/v fp16 (q scaled by QSCALE). MODE 1: fp32 C.
// ---------------------------------------------------------------------------
#define GEMM_BUF_HALVES (2 * BM * LDH)                    // A+B per stage
#define GEMM_SMEM_BYTES (3 * GEMM_BUF_HALVES * 2)         // 108 KB

template <int MODE>
__global__ __launch_bounds__(256, 2)
void tc_gemm(const __half* __restrict__ A, const __half* __restrict__ W,
             const float* __restrict__ bias, float* __restrict__ C,
             __half* __restrict__ Qo, __half* __restrict__ Ko, __half* __restrict__ Vo)
{
    extern __shared__ char smraw[];
    __half* sbuf = (__half*)smraw;

    const int tid    = threadIdx.x;
    const int wid    = tid >> 5;
    const int lane   = tid & 31;
    const int warp_m = wid & 3;
    const int warp_n = wid >> 2;
    const int m0     = blockIdx.y * BM;
    const int n0     = blockIdx.x * BN;

    const int len = g_len[m0 >> 10];
    if ((m0 & 1023) >= len) {
        if (MODE == 0) return;
        for (int idx = tid; idx < BM * (EE / 4); idx += 256) {
            const int row = idx / (EE / 4);
            const int c4  = idx % (EE / 4);
            *(float4*)(C + (size_t)(m0 + row) * EE + c4 * 4) =
                *(const float4*)(bias + c4 * 4);
        }
        return;
    }

    const __half* Abase = A + (size_t)m0 * EE;
    const __half* Wbase = W + (size_t)n0 * EE;

    float acc[2][8][4];
#pragma unroll
    for (int i = 0; i < 2; ++i)
#pragma unroll
        for (int j = 0; j < 8; ++j)
#pragma unroll
            for (int r = 0; r < 4; ++r) acc[i][j][r] = 0.f;

    auto issue_tile = [&](int t, int buf) {
        const __half* Ag = Abase + t * BK;
        const __half* Wg = Wbase + t * BK;
        __half* sA = sbuf + buf * GEMM_BUF_HALVES;
        __half* sB = sA + BM * LDH;
#pragma unroll
        for (int i = 0; i < 4; ++i) {
            const int idx = tid + (i << 8);
            const int row = idx >> 3;
            const int seg = idx & 7;
            const __half* srcA = Ag + (size_t)row * EE + seg * 8;
            const __half* srcB = Wg + (size_t)row * EE + seg * 8;
            uint32_t dA = (uint32_t)__cvta_generic_to_shared(sA + row * LDH + seg * 8);
            uint32_t dB = (uint32_t)__cvta_generic_to_shared(sB + row * LDH + seg * 8);
            asm volatile("cp.async.cg.shared.global [%0], [%1], 16;" :: "r"(dA), "l"(srcA));
            asm volatile("cp.async.cg.shared.global [%0], [%1], 16;" :: "r"(dB), "l"(srcB));
        }
        asm volatile("cp.async.commit_group;" ::: "memory");
    };

    // hoisted ldmatrix lane bases (byte addresses in shared window)
    const int ar  = lane & 15;
    const int ac8 = (lane >> 4) * 8;
    const int br  = ((lane >> 4) & 1) * 8 + (lane & 7);
    const int bc8 = ((lane >> 3) & 1) * 8;
    const uint32_t sb0   = (uint32_t)__cvta_generic_to_shared(sbuf);
    const uint32_t aBase = sb0 + (uint32_t)(((warp_m * 32 + ar) * LDH + ac8) * 2);
    const uint32_t bBase = sb0 + (uint32_t)(BM * LDH * 2)
                               + (uint32_t)(((warp_n * 64 + br) * LDH + bc8) * 2);

    const int nT = EE / BK;    // 12
    issue_tile(0, 0);
    issue_tile(1, 1);

    int buf = 0, nb = 2;
    for (int t = 0; t < nT; ++t) {
        asm volatile("cp.async.wait_group 1;" ::: "memory");
        __syncthreads();   // buffer `buf` ready; all warps done with buf(t-1)

        if (t + 2 < nT) issue_tile(t + 2, nb);
        else            asm volatile("cp.async.commit_group;" ::: "memory");

        const uint32_t bufOff = (uint32_t)buf * (GEMM_BUF_HALVES * 2);
        const uint32_t aOff = aBase + bufOff;
        const uint32_t bOff = bBase + bufOff;
#pragma unroll
        for (int kk = 0; kk < BK / 16; ++kk) {
            uint32_t af[2][4];
#pragma unroll
            for (int i = 0; i < 2; ++i)
                LDMATRIX_X4(af[i], aOff + (uint32_t)((i * 16 * LDH + kk * 16) * 2));
#pragma unroll
            for (int jc = 0; jc < 8; jc += 2) {
                uint32_t kb[4];
                LDMATRIX_X4(kb, bOff + (uint32_t)((jc * 8 * LDH + kk * 16) * 2));
#pragma unroll
                for (int i = 0; i < 2; ++i) {
                    MMA16816(acc[i][jc],     af[i], kb);
                    MMA16816(acc[i][jc + 1], af[i], kb + 2);
                }
            }
        }
        buf = (buf == 2) ? 0 : buf + 1;
        nb  = (nb  == 2) ? 0 : nb  + 1;
        // no trailing sync: next iteration's barrier protects buffer reuse
    }

    const int gid = lane >> 2;
    const int t4  = lane & 3;
#pragma unroll
    for (int i = 0; i < 2; ++i) {
        const int mrow = m0 + warp_m * 32 + i * 16 + gid;
#pragma unroll
        for (int jc = 0; jc < 8; ++jc) {
            const int n = n0 + warp_n * 64 + jc * 8 + t4 * 2;
            const float2 bv = *(const float2*)(bias + n);
            float ox0 = acc[i][jc][0] + bv.x, oy0 = acc[i][jc][1] + bv.y;
            float ox1 = acc[i][jc][2] + bv.x, oy1 = acc[i][jc][3] + bv.y;
            if (MODE == 0) {
                const int c  = n / EE;
                const int rr = n - c * EE;
                const int h  = rr >> 6;
                const int d  = rr & 63;
                if (c == 0) { ox0 *= QSCALE; oy0 *= QSCALE; ox1 *= QSCALE; oy1 *= QSCALE; }
                __half* dst = ((c == 0) ? Qo : (c == 1) ? Ko : Vo);
                const int b = mrow >> 10;
                const int s = mrow & 1023;
                __half* p0 = dst + ((((size_t)b * HH + h) * SS + s) * DD + d);
                *(__half2*)p0                      = __floats2half2_rn(ox0, oy0);
                *(__half2*)(p0 + (size_t)8 * DD)   = __floats2half2_rn(ox1, oy1);
            } else {
                *(float2*)(C + (size_t)mrow * EE + n)       = make_float2(ox0, oy0);
                *(float2*)(C + (size_t)(mrow + 8) * EE + n) = make_float2(ox1, oy1);
            }
        }
    }
}

// ---------------------------------------------------------------------------
// Flash attention v6: register-resident FA2, exp2 softmax, 3-stage K/V ring,
// one __syncthreads per tile, hoisted ldmatrix bases, 2 CTAs/SM.
// smem: sQ 128x72 | sK 3x(64x72) | sV 3x(64x72) = 72 KB
// ---------------------------------------------------------------------------
#define ATT_KV_HALVES (64 * ATT_LDH)
#define ATT_SMEM_BYTES ((128 * ATT_LDH + 6 * ATT_KV_HALVES) * 2)

__global__ __launch_bounds__(256, 2)
void attn_kernel(const __half* __restrict__ qh, const __half* __restrict__ kh,
                 const __half* __restrict__ vh, __half* __restrict__ ctxh)
{
    extern __shared__ char smraw[];
    __half* sQ  = (__half*)smraw;                        // 128 x 72
    __half* sK0 = sQ + 128 * ATT_LDH;                    // 3 x (64 x 72)
    __half* sV0 = sK0 + 3 * ATT_KV_HALVES;               // 3 x (64 x 72)

    const int tid  = threadIdx.x;
    const int wid  = tid >> 5;
    const int lane = tid & 31;
    const int gid  = lane >> 2;
    const int t4   = lane & 3;
    const int hh   = blockIdx.y;
    const int bb   = blockIdx.z;
    const int bh   = bb * HH + hh;
    const int q0   = blockIdx.x * 128;
    const int len  = g_len[bb];

    if (q0 >= len) return;   // gemm1's bias-fill never reads these ctx rows

    const uint4* kg = (const uint4*)(kh + (size_t)bh * SS * DD);
    const uint4* vg = (const uint4*)(vh + (size_t)bh * SS * DD);

    auto issue_kv = [&](int j0, int buf) {
        __half* dK = sK0 + buf * ATT_KV_HALVES;
        __half* dV = sV0 + buf * ATT_KV_HALVES;
#pragma unroll
        for (int i = 0; i < 2; ++i) {
            const int idx = tid + (i << 8);
            const int r = idx >> 3, seg = idx & 7;
            const uint4* sk = &kg[(j0 + r) * 8 + seg];
            const uint4* sv = &vg[(j0 + r) * 8 + seg];
            uint32_t aK = (uint32_t)__cvta_generic_to_shared(dK + r * ATT_LDH + seg * 8);
            uint32_t aV = (uint32_t)__cvta_generic_to_shared(dV + r * ATT_LDH + seg * 8);
            asm volatile("cp.async.cg.shared.global [%0], [%1], 16;" :: "r"(aK), "l"(sk));
            asm volatile("cp.async.cg.shared.global [%0], [%1], 16;" :: "r"(aV), "l"(sv));
        }
        asm volatile("cp.async.commit_group;" ::: "memory");
    };

    const int nTiles = (len + 63) >> 6;

    issue_kv(0, 0);
    if (nTiles > 1) issue_kv(64, 1);
    else            asm volatile("cp.async.commit_group;" ::: "memory");

    // stage Q while tile 0 is in flight
    {
        const uint4* qg = (const uint4*)(qh + ((size_t)bh * SS + q0) * DD);
#pragma unroll
        for (int i = 0; i < 4; ++i) {
            const int idx = tid + (i << 8);
            const int r = idx >> 3, seg = idx & 7;
            *(uint4*)(sQ + r * ATT_LDH + seg * 8) = qg[r * 8 + seg];
        }
    }
    __syncthreads();

    uint32_t qa[4][4];
    {
        const int r  = wid * 16 + (lane & 15);
        const int c8 = (lane >> 4) * 8;
#pragma unroll
        for (int kk = 0; kk < 4; ++kk) {
            uint32_t a = (uint32_t)__cvta_generic_to_shared(sQ + r * ATT_LDH + kk * 16 + c8);
            LDMATRIX_X4(qa[kk], a);
        }
    }

    // hoisted K/V ldmatrix lane bases
    const int krb = ((lane >> 4) & 1) * 8 + (lane & 7);
    const int kcb = ((lane >> 3) & 1) * 8;
    const int vrb = ((lane >> 3) & 1) * 8 + (lane & 7);
    const int vcb = (lane >> 4) * 8;
    const uint32_t kBase = (uint32_t)__cvta_generic_to_shared(sK0)
                         + (uint32_t)((krb * ATT_LDH + kcb) * 2);
    const uint32_t vBase = (uint32_t)__cvta_generic_to_shared(sV0)
                         + (uint32_t)((vrb * ATT_LDH + vcb) * 2);

    float oacc[8][4];
#pragma unroll
    for (int i = 0; i < 8; ++i)
#pragma unroll
        for (int j = 0; j < 4; ++j) oacc[i][j] = 0.f;
    float m0r = -1e30f, m1r = -1e30f, l0 = 0.f, l1 = 0.f;

    int buf = 0, nb = 2;
    for (int t = 0; t < nTiles; ++t) {
        const int j0 = t << 6;

        asm volatile("cp.async.wait_group 1;" ::: "memory");
        __syncthreads();   // buffer `buf` filled & visible; all warps past t-1

        if (t + 2 < nTiles) issue_kv(j0 + 128, nb);
        else                asm volatile("cp.async.commit_group;" ::: "memory");

        const uint32_t kvOff = (uint32_t)buf * (ATT_KV_HALVES * 2);
        const uint32_t kOff = kBase + kvOff;
        const uint32_t vOff = vBase + kvOff;

        float sacc[8][4];
#pragma unroll
        for (int i = 0; i < 8; ++i)
#pragma unroll
            for (int j = 0; j < 4; ++j) sacc[i][j] = 0.f;

#pragma unroll
        for (int kk = 0; kk < 4; ++kk) {
#pragma unroll
            for (int jc = 0; jc < 8; jc += 2) {
                uint32_t kb[4];
                LDMATRIX_X4(kb, kOff + (uint32_t)((jc * 8 * ATT_LDH + kk * 16) * 2));
                MMA16816(sacc[jc],     qa[kk], kb);
                MMA16816(sacc[jc + 1], qa[kk], kb + 2);
            }
        }

        const int nk = min(64, len - j0);
        if (nk < 64) {
#pragma unroll
            for (int jc = 0; jc < 8; ++jc) {
                const int c = jc * 8 + t4 * 2;
                if (c     >= nk) { sacc[jc][0] = -1e30f; sacc[jc][2] = -1e30f; }
                if (c + 1 >= nk) { sacc[jc][1] = -1e30f; sacc[jc][3] = -1e30f; }
            }
        }
        float mt0 = -1e30f, mt1 = -1e30f;
#pragma unroll
        for (int jc = 0; jc < 8; ++jc) {
            mt0 = fmaxf(mt0, fmaxf(sacc[jc][0], sacc[jc][1]));
            mt1 = fmaxf(mt1, fmaxf(sacc[jc][2], sacc[jc][3]));
        }
        mt0 = fmaxf(mt0, __shfl_xor_sync(0xffffffffu, mt0, 1));
        mt0 = fmaxf(mt0, __shfl_xor_sync(0xffffffffu, mt0, 2));
        mt1 = fmaxf(mt1, __shfl_xor_sync(0xffffffffu, mt1, 1));
        mt1 = fmaxf(mt1, __shfl_xor_sync(0xffffffffu, mt1, 2));

        const float mn0 = fmaxf(m0r, mt0), mn1 = fmaxf(m1r, mt1);
        const float corr0 = exp2f(m0r - mn0), corr1 = exp2f(m1r - mn1);
        m0r = mn0; m1r = mn1;

        float ls0 = 0.f, ls1 = 0.f;
#pragma unroll
        for (int jc = 0; jc < 8; ++jc) {
            sacc[jc][0] = exp2f(sacc[jc][0] - mn0);
            sacc[jc][1] = exp2f(sacc[jc][1] - mn0);
            sacc[jc][2] = exp2f(sacc[jc][2] - mn1);
            sacc[jc][3] = exp2f(sacc[jc][3] - mn1);
            ls0 += sacc[jc][0] + sacc[jc][1];
            ls1 += sacc[jc][2] + sacc[jc][3];
        }
        ls0 += __shfl_xor_sync(0xffffffffu, ls0, 1);
        ls0 += __shfl_xor_sync(0xffffffffu, ls0, 2);
        ls1 += __shfl_xor_sync(0xffffffffu, ls1, 1);
        ls1 += __shfl_xor_sync(0xffffffffu, ls1, 2);
        l0 = l0 * corr0 + ls0;
        l1 = l1 * corr1 + ls1;

#pragma unroll
        for (int nc = 0; nc < 8; ++nc) {
            oacc[nc][0] *= corr0; oacc[nc][1] *= corr0;
            oacc[nc][2] *= corr1; oacc[nc][3] *= corr1;
        }

#pragma unroll
        for (int kk = 0; kk < 4; ++kk) {
            uint32_t pa[4];
            pa[0] = packh2(sacc[2 * kk][0],     sacc[2 * kk][1]);
            pa[1] = packh2(sacc[2 * kk][2],     sacc[2 * kk][3]);
            pa[2] = packh2(sacc[2 * kk + 1][0], sacc[2 * kk + 1][1]);
            pa[3] = packh2(sacc[2 * kk + 1][2], sacc[2 * kk + 1][3]);
#pragma unroll
            for (int nc = 0; nc < 8; nc += 2) {
                uint32_t vb[4];
                LDMATRIX_X4_T(vb, vOff + (uint32_t)((kk * 16 * ATT_LDH + nc * 8) * 2));
                MMA16816(oacc[nc],     pa, vb);
                MMA16816(oacc[nc + 1], pa, vb + 2);
            }
        }

        buf = (buf == 2) ? 0 : buf + 1;
        nb  = (nb  == 2) ? 0 : nb  + 1;
        // no trailing sync: next iteration's barrier protects buffer reuse
    }

    const int qrow0 = q0 + wid * 16 + gid;
    const float fin0 = (qrow0     < len) ? (1.0f / l0) : 0.f;
    const float fin1 = (qrow0 + 8 < len) ? (1.0f / l1) : 0.f;
    __half* base0 = ctxh + ((size_t)bb * SS + qrow0) * EE + hh * DD;
    __half* base1 = base0 + (size_t)8 * EE;
#pragma unroll
    for (int nc = 0; nc < 8; ++nc) {
        const int d = nc * 8 + t4 * 2;
        *(__half2*)(base0 + d) = __floats2half2_rn(oacc[nc][0] * fin0, oacc[nc][1] * fin0);
        *(__half2*)(base1 + d) = __floats2half2_rn(oacc[nc][2] * fin1, oacc[nc][3] * fin1);
    }
}

// ---------------------------------------------------------------------------
// Launch
// ---------------------------------------------------------------------------
extern "C" void kernel_launch(void* const* d_in, const int* in_sizes, int n_in,
                              void* d_out, int out_size)
{
    const float* x            = (const float*)d_in[0];
    const unsigned char* mask = (const unsigned char*)d_in[1];
    const float* Wqkv_w       = (const float*)d_in[2];
    const float* Wqkv_b       = (const float*)d_in[3];
    const float* out_w        = (const float*)d_in[4];
    const float* out_b        = (const float*)d_in[5];
    float* out                = (float*)d_out;

    __half *xh, *wqkvh, *owh, *qh, *kh, *vh, *ctxh;
    cudaGetSymbolAddress((void**)&xh,    g_xh);
    cudaGetSymbolAddress((void**)&wqkvh, g_wqkvh);
    cudaGetSymbolAddress((void**)&owh,   g_owh);
    cudaGetSymbolAddress((void**)&qh,    g_qh);
    cudaGetSymbolAddress((void**)&kh,    g_kh);
    cudaGetSymbolAddress((void**)&vh,    g_vh);
    cudaGetSymbolAddress((void**)&ctxh,  g_ctxh);

    // 1) lengths + fused fp16 conversion (one launch)
    lengths_kernel<<<BB, 32>>>(mask);
    conv_all<<<(CN1 + CN2 + CN3 + 255) / 256, 256>>>(x, Wqkv_w, out_w);

    // 2) QKV projection (3-stage ring mma.sync GEMM + padded-slab skip)
    cudaFuncSetAttribute(tc_gemm<0>, cudaFuncAttributeMaxDynamicSharedMemorySize, GEMM_SMEM_BYTES);
    cudaFuncSetAttribute(tc_gemm<1>, cudaFuncAttributeMaxDynamicSharedMemorySize, GEMM_SMEM_BYTES);
    {
        dim3 grid(3 * EE / BN, (BB * SS) / BM);
        tc_gemm<0><<<grid, 256, GEMM_SMEM_BYTES>>>(xh, wqkvh, Wqkv_b, nullptr, qh, kh, vh);
    }

    // 3) flash attention (3-stage ring, hoisted addresses) -> ctx fp16
    cudaFuncSetAttribute(attn_kernel, cudaFuncAttributeMaxDynamicSharedMemorySize, ATT_SMEM_BYTES);
    attn_kernel<<<dim3(SS / 128, HH, BB), 256, ATT_SMEM_BYTES>>>(qh, kh, vh, ctxh);

    // 4) output projection (3-stage ring + bias-fill for padded slabs)
    {
        dim3 grid(EE / BN, (BB * SS) / BM);
        tc_gemm<1><<<grid, 256, GEMM_SMEM_BYTES>>>(ctxh, owh, out_b, out, nullptr, nullptr, nullptr);
    }
}

// round 12
// speedup vs baseline: 1.0012x; 1.0012x over previous
#include <cuda_runtime.h>
#include <cuda_fp16.h>
#include <math.h>
#include <stdint.h>

// Problem constants
#define BB 8
#define SS 1024
#define EE 768
#define HH 12
#define DD 64

// GEMM tiling
#define BM 128
#define BN 128
#define BK 64
#define LDH 72            // padded halves stride in smem tiles

// Attention smem stride (halves)
#define ATT_LDH 72

// q pre-scale: 1/sqrt(64) * log2(e)  (softmax runs in exp2 domain)
#define QSCALE (0.125f * 1.4426950408889634f)

// Scratch (allocation-free rule: __device__ globals)
__device__ __half g_xh[(size_t)BB * SS * EE];
__device__ __half g_wqkvh[(size_t)3 * EE * EE];
__device__ __half g_owh[(size_t)EE * EE];
__device__ __half g_qh[(size_t)BB * HH * SS * DD];
__device__ __half g_kh[(size_t)BB * HH * SS * DD];
__device__ __half g_vh[(size_t)BB * HH * SS * DD];
__device__ __half g_ctxh[(size_t)BB * SS * EE];
__device__ int    g_len[BB];

__device__ __forceinline__ uint32_t packh2(float a, float b) {
    __half2 h = __floats2half2_rn(a, b);
    return *(uint32_t*)&h;
}

#define MMA16816(C, A, B)                                                      \
    asm volatile("mma.sync.aligned.m16n8k16.row.col.f32.f16.f16.f32 "          \
        "{%0,%1,%2,%3}, {%4,%5,%6,%7}, {%8,%9}, {%0,%1,%2,%3};"                \
        : "+f"((C)[0]), "+f"((C)[1]), "+f"((C)[2]), "+f"((C)[3])               \
        : "r"((A)[0]), "r"((A)[1]), "r"((A)[2]), "r"((A)[3]),                  \
          "r"((B)[0]), "r"((B)[1]))

#define LDMATRIX_X4(R, ADDR)                                                   \
    asm volatile("ldmatrix.sync.aligned.m8n8.x4.shared.b16 {%0,%1,%2,%3}, [%4];" \
        : "=r"((R)[0]), "=r"((R)[1]), "=r"((R)[2]), "=r"((R)[3]) : "r"(ADDR))

#define LDMATRIX_X4_T(R, ADDR)                                                 \
    asm volatile("ldmatrix.sync.aligned.m8n8.x4.trans.shared.b16 {%0,%1,%2,%3}, [%4];" \
        : "=r"((R)[0]), "=r"((R)[1]), "=r"((R)[2]), "=r"((R)[3]) : "r"(ADDR))

// ---------------------------------------------------------------------------
// Fused fp32 -> fp16 conversion for x, Wqkv_w, out_w (one launch)
// ---------------------------------------------------------------------------
#define CN1 (BB * SS * EE / 4)
#define CN2 (3 * EE * EE / 4)
#define CN3 (EE * EE / 4)

__global__ void conv_all(const float* __restrict__ x, const float* __restrict__ w1,
                         const float* __restrict__ w2)
{
    int i = blockIdx.x * 256 + threadIdx.x;
    const float* src;
    __half* dst;
    if (i < CN1)              { src = x;  dst = g_xh; }
    else if (i < CN1 + CN2)   { src = w1; dst = g_wqkvh; i -= CN1; }
    else if (i < CN1+CN2+CN3) { src = w2; dst = g_owh;   i -= CN1 + CN2; }
    else return;
    const float4 v = ((const float4*)src)[i];
    ((__half2*)dst)[i * 2]     = __floats2half2_rn(v.x, v.y);
    ((__half2*)dst)[i * 2 + 1] = __floats2half2_rn(v.z, v.w);
}

// ---------------------------------------------------------------------------
// Mask -> per-batch valid length (prefix mask; count nonzeros).
// ---------------------------------------------------------------------------
__global__ void lengths_kernel(const unsigned char* __restrict__ mask)
{
    const int b = blockIdx.x;
    const int lane = threadIdx.x;
    int cnt = 0;
    if (mask[1] != 0) {
        const unsigned char* row = mask + (size_t)b * SS;
        for (int i = lane; i < SS; i += 32) cnt += (row[i] != 0);
    } else {
        const unsigned int* row = (const unsigned int*)mask + (size_t)b * SS;
        for (int i = lane; i < SS; i += 32) cnt += (row[i] != 0u);
    }
#pragma unroll
    for (int o = 16; o; o >>= 1) cnt += __shfl_xor_sync(0xffffffffu, cnt, o);
    if (lane == 0) g_len[b] = cnt;
}

// ---------------------------------------------------------------------------
// fp16 GEMM via raw mma.sync + ldmatrix.
// 3-stage cp.async ring, ONE __syncthreads per k-iteration, hoisted
// ldmatrix base addresses. CTA 128x128, BK=64, 8 warps (4m x 2n).
// MODE 0: scatter q/k/v fp16 (q scaled by QSCALE). MODE 1: fp32 C.
// ---------------------------------------------------------------------------
#define GEMM_BUF_HALVES (2 * BM * LDH)                    // A+B per stage
#define GEMM_SMEM_BYTES (3 * GEMM_BUF_HALVES * 2)         // 108 KB

template <int MODE>
__global__ __launch_bounds__(256, 2)
void tc_gemm(const __half* __restrict__ A, const __half* __restrict__ W,
             const float* __restrict__ bias, float* __restrict__ C,
             __half* __restrict__ Qo, __half* __restrict__ Ko, __half* __restrict__ Vo)
{
    extern __shared__ char smraw[];
    __half* sbuf = (__half*)smraw;

    const int tid    = threadIdx.x;
    const int wid    = tid >> 5;
    const int lane   = tid & 31;
    const int warp_m = wid & 3;
    const int warp_n = wid >> 2;
    const int m0     = blockIdx.y * BM;
    const int n0     = blockIdx.x * BN;

    const int len = g_len[m0 >> 10];
    if ((m0 & 1023) >= len) {
        if (MODE == 0) return;
        for (int idx = tid; idx < BM * (EE / 4); idx += 256) {
            const int row = idx / (EE / 4);
            const int c4  = idx % (EE / 4);
            *(float4*)(C + (size_t)(m0 + row) * EE + c4 * 4) =
                *(const float4*)(bias + c4 * 4);
        }
        return;
    }

    const __half* Abase = A + (size_t)m0 * EE;
    const __half* Wbase = W + (size_t)n0 * EE;

    float acc[2][8][4];
#pragma unroll
    for (int i = 0; i < 2; ++i)
#pragma unroll
        for (int j = 0; j < 8; ++j)
#pragma unroll
            for (int r = 0; r < 4; ++r) acc[i][j][r] = 0.f;

    auto issue_tile = [&](int t, int buf) {
        const __half* Ag = Abase + t * BK;
        const __half* Wg = Wbase + t * BK;
        __half* sA = sbuf + buf * GEMM_BUF_HALVES;
        __half* sB = sA + BM * LDH;
#pragma unroll
        for (int i = 0; i < 4; ++i) {
            const int idx = tid + (i << 8);
            const int row = idx >> 3;
            const int seg = idx & 7;
            const __half* srcA = Ag + (size_t)row * EE + seg * 8;
            const __half* srcB = Wg + (size_t)row * EE + seg * 8;
            uint32_t dA = (uint32_t)__cvta_generic_to_shared(sA + row * LDH + seg * 8);
            uint32_t dB = (uint32_t)__cvta_generic_to_shared(sB + row * LDH + seg * 8);
            asm volatile("cp.async.cg.shared.global [%0], [%1], 16;" :: "r"(dA), "l"(srcA));
            asm volatile("cp.async.cg.shared.global [%0], [%1], 16;" :: "r"(dB), "l"(srcB));
        }
        asm volatile("cp.async.commit_group;" ::: "memory");
    };

    // hoisted ldmatrix lane bases (byte addresses in shared window)
    const int ar  = lane & 15;
    const int ac8 = (lane >> 4) * 8;
    const int br  = ((lane >> 4) & 1) * 8 + (lane & 7);
    const int bc8 = ((lane >> 3) & 1) * 8;
    const uint32_t sb0   = (uint32_t)__cvta_generic_to_shared(sbuf);
    const uint32_t aBase = sb0 + (uint32_t)(((warp_m * 32 + ar) * LDH + ac8) * 2);
    const uint32_t bBase = sb0 + (uint32_t)(BM * LDH * 2)
                               + (uint32_t)(((warp_n * 64 + br) * LDH + bc8) * 2);

    const int nT = EE / BK;    // 12
    issue_tile(0, 0);
    issue_tile(1, 1);

    int buf = 0, nb = 2;
    for (int t = 0; t < nT; ++t) {
        asm volatile("cp.async.wait_group 1;" ::: "memory");
        __syncthreads();   // buffer `buf` ready; all warps done with buf(t-1)

        if (t + 2 < nT) issue_tile(t + 2, nb);
        else            asm volatile("cp.async.commit_group;" ::: "memory");

        const uint32_t bufOff = (uint32_t)buf * (GEMM_BUF_HALVES * 2);
        const uint32_t aOff = aBase + bufOff;
        const uint32_t bOff = bBase + bufOff;
#pragma unroll
        for (int kk = 0; kk < BK / 16; ++kk) {
            uint32_t af[2][4];
#pragma unroll
            for (int i = 0; i < 2; ++i)
                LDMATRIX_X4(af[i], aOff + (uint32_t)((i * 16 * LDH + kk * 16) * 2));
#pragma unroll
            for (int jc = 0; jc < 8; jc += 2) {
                uint32_t kb[4];
                LDMATRIX_X4(kb, bOff + (uint32_t)((jc * 8 * LDH + kk * 16) * 2));
#pragma unroll
                for (int i = 0; i < 2; ++i) {
                    MMA16816(acc[i][jc],     af[i], kb);
                    MMA16816(acc[i][jc + 1], af[i], kb + 2);
                }
            }
        }
        buf = (buf == 2) ? 0 : buf + 1;
        nb  = (nb  == 2) ? 0 : nb  + 1;
        // no trailing sync: next iteration's barrier protects buffer reuse
    }

    const int gid = lane >> 2;
    const int t4  = lane & 3;
#pragma unroll
    for (int i = 0; i < 2; ++i) {
        const int mrow = m0 + warp_m * 32 + i * 16 + gid;
#pragma unroll
        for (int jc = 0; jc < 8; ++jc) {
            const int n = n0 + warp_n * 64 + jc * 8 + t4 * 2;
            const float2 bv = *(const float2*)(bias + n);
            float ox0 = acc[i][jc][0] + bv.x, oy0 = acc[i][jc][1] + bv.y;
            float ox1 = acc[i][jc][2] + bv.x, oy1 = acc[i][jc][3] + bv.y;
            if (MODE == 0) {
                const int c  = n / EE;
                const int rr = n - c * EE;
                const int h  = rr >> 6;
                const int d  = rr & 63;
                if (c == 0) { ox0 *= QSCALE; oy0 *= QSCALE; ox1 *= QSCALE; oy1 *= QSCALE; }
                __half* dst = ((c == 0) ? Qo : (c == 1) ? Ko : Vo);
                const int b = mrow >> 10;
                const int s = mrow & 1023;
                __half* p0 = dst + ((((size_t)b * HH + h) * SS + s) * DD + d);
                *(__half2*)p0                      = __floats2half2_rn(ox0, oy0);
                *(__half2*)(p0 + (size_t)8 * DD)   = __floats2half2_rn(ox1, oy1);
            } else {
                *(float2*)(C + (size_t)mrow * EE + n)       = make_float2(ox0, oy0);
                *(float2*)(C + (size_t)(mrow + 8) * EE + n) = make_float2(ox1, oy1);
            }
        }
    }
}

// ---------------------------------------------------------------------------
// Flash attention v6: register-resident FA2, exp2 softmax, 3-stage K/V ring,
// one __syncthreads per tile, hoisted ldmatrix bases, 2 CTAs/SM.
// smem: sQ 128x72 | sK 3x(64x72) | sV 3x(64x72) = 72 KB
// ---------------------------------------------------------------------------
#define ATT_KV_HALVES (64 * ATT_LDH)
#define ATT_SMEM_BYTES ((128 * ATT_LDH + 6 * ATT_KV_HALVES) * 2)

__global__ __launch_bounds__(256, 2)
void attn_kernel(const __half* __restrict__ qh, const __half* __restrict__ kh,
                 const __half* __restrict__ vh, __half* __restrict__ ctxh)
{
    extern __shared__ char smraw[];
    __half* sQ  = (__half*)smraw;                        // 128 x 72
    __half* sK0 = sQ + 128 * ATT_LDH;                    // 3 x (64 x 72)
    __half* sV0 = sK0 + 3 * ATT_KV_HALVES;               // 3 x (64 x 72)

    const int tid  = threadIdx.x;
    const int wid  = tid >> 5;
    const int lane = tid & 31;
    const int gid  = lane >> 2;
    const int t4   = lane & 3;
    const int hh   = blockIdx.y;
    const int bb   = blockIdx.z;
    const int bh   = bb * HH + hh;
    const int q0   = blockIdx.x * 128;
    const int len  = g_len[bb];

    if (q0 >= len) return;   // gemm1's bias-fill never reads these ctx rows

    const uint4* kg = (const uint4*)(kh + (size_t)bh * SS * DD);
    const uint4* vg = (const uint4*)(vh + (size_t)bh * SS * DD);

    auto issue_kv = [&](int j0, int buf) {
        __half* dK = sK0 + buf * ATT_KV_HALVES;
        __half* dV = sV0 + buf * ATT_KV_HALVES;
#pragma unroll
        for (int i = 0; i < 2; ++i) {
            const int idx = tid + (i << 8);
            const int r = idx >> 3, seg = idx & 7;
            const uint4* sk = &kg[(j0 + r) * 8 + seg];
            const uint4* sv = &vg[(j0 + r) * 8 + seg];
            uint32_t aK = (uint32_t)__cvta_generic_to_shared(dK + r * ATT_LDH + seg * 8);
            uint32_t aV = (uint32_t)__cvta_generic_to_shared(dV + r * ATT_LDH + seg * 8);
            asm volatile("cp.async.cg.shared.global [%0], [%1], 16;" :: "r"(aK), "l"(sk));
            asm volatile("cp.async.cg.shared.global [%0], [%1], 16;" :: "r"(aV), "l"(sv));
        }
        asm volatile("cp.async.commit_group;" ::: "memory");
    };

    const int nTiles = (len + 63) >> 6;

    issue_kv(0, 0);
    if (nTiles > 1) issue_kv(64, 1);
    else            asm volatile("cp.async.commit_group;" ::: "memory");

    // stage Q while tile 0 is in flight
    {
        const uint4* qg = (const uint4*)(qh + ((size_t)bh * SS + q0) * DD);
#pragma unroll
        for (int i = 0; i < 4; ++i) {
            const int idx = tid + (i << 8);
            const int r = idx >> 3, seg = idx & 7;
            *(uint4*)(sQ + r * ATT_LDH + seg * 8) = qg[r * 8 + seg];
        }
    }
    __syncthreads();

    uint32_t qa[4][4];
    {
        const int r  = wid * 16 + (lane & 15);
        const int c8 = (lane >> 4) * 8;
#pragma unroll
        for (int kk = 0; kk < 4; ++kk) {
            uint32_t a = (uint32_t)__cvta_generic_to_shared(sQ + r * ATT_LDH + kk * 16 + c8);
            LDMATRIX_X4(qa[kk], a);
        }
    }

    // hoisted K/V ldmatrix lane bases
    const int krb = ((lane >> 4) & 1) * 8 + (lane & 7);
    const int kcb = ((lane >> 3) & 1) * 8;
    const int vrb = ((lane >> 3) & 1) * 8 + (lane & 7);
    const int vcb = (lane >> 4) * 8;
    const uint32_t kBase = (uint32_t)__cvta_generic_to_shared(sK0)
                         + (uint32_t)((krb * ATT_LDH + kcb) * 2);
    const uint32_t vBase = (uint32_t)__cvta_generic_to_shared(sV0)
                         + (uint32_t)((vrb * ATT_LDH + vcb) * 2);

    float oacc[8][4];
#pragma unroll
    for (int i = 0; i < 8; ++i)
#pragma unroll
        for (int j = 0; j < 4; ++j) oacc[i][j] = 0.f;
    float m0r = -1e30f, m1r = -1e30f, l0 = 0.f, l1 = 0.f;

    int buf = 0, nb = 2;
    for (int t = 0; t < nTiles; ++t) {
        const int j0 = t << 6;

        asm volatile("cp.async.wait_group 1;" ::: "memory");
        __syncthreads();   // buffer `buf` filled & visible; all warps past t-1

        if (t + 2 < nTiles) issue_kv(j0 + 128, nb);
        else                asm volatile("cp.async.commit_group;" ::: "memory");

        const uint32_t kvOff = (uint32_t)buf * (ATT_KV_HALVES * 2);
        const uint32_t kOff = kBase + kvOff;
        const uint32_t vOff = vBase + kvOff;

        float sacc[8][4];
#pragma unroll
        for (int i = 0; i < 8; ++i)
#pragma unroll
            for (int j = 0; j < 4; ++j) sacc[i][j] = 0.f;

#pragma unroll
        for (int kk = 0; kk < 4; ++kk) {
#pragma unroll
            for (int jc = 0; jc < 8; jc += 2) {
                uint32_t kb[4];
                LDMATRIX_X4(kb, kOff + (uint32_t)((jc * 8 * ATT_LDH + kk * 16) * 2));
                MMA16816(sacc[jc],     qa[kk], kb);
                MMA16816(sacc[jc + 1], qa[kk], kb + 2);
            }
        }

        const int nk = min(64, len - j0);
        if (nk < 64) {
#pragma unroll
            for (int jc = 0; jc < 8; ++jc) {
                const int c = jc * 8 + t4 * 2;
                if (c     >= nk) { sacc[jc][0] = -1e30f; sacc[jc][2] = -1e30f; }
                if (c + 1 >= nk) { sacc[jc][1] = -1e30f; sacc[jc][3] = -1e30f; }
            }
        }
        float mt0 = -1e30f, mt1 = -1e30f;
#pragma unroll
        for (int jc = 0; jc < 8; ++jc) {
            mt0 = fmaxf(mt0, fmaxf(sacc[jc][0], sacc[jc][1]));
            mt1 = fmaxf(mt1, fmaxf(sacc[jc][2], sacc[jc][3]));
        }
        mt0 = fmaxf(mt0, __shfl_xor_sync(0xffffffffu, mt0, 1));
        mt0 = fmaxf(mt0, __shfl_xor_sync(0xffffffffu, mt0, 2));
        mt1 = fmaxf(mt1, __shfl_xor_sync(0xffffffffu, mt1, 1));
        mt1 = fmaxf(mt1, __shfl_xor_sync(0xffffffffu, mt1, 2));

        const float mn0 = fmaxf(m0r, mt0), mn1 = fmaxf(m1r, mt1);
        const float corr0 = exp2f(m0r - mn0), corr1 = exp2f(m1r - mn1);
        m0r = mn0; m1r = mn1;

        float ls0 = 0.f, ls1 = 0.f;
#pragma unroll
        for (int jc = 0; jc < 8; ++jc) {
            sacc[jc][0] = exp2f(sacc[jc][0] - mn0);
            sacc[jc][1] = exp2f(sacc[jc][1] - mn0);
            sacc[jc][2] = exp2f(sacc[jc][2] - mn1);
            sacc[jc][3] = exp2f(sacc[jc][3] - mn1);
            ls0 += sacc[jc][0] + sacc[jc][1];
            ls1 += sacc[jc][2] + sacc[jc][3];
        }
        ls0 += __shfl_xor_sync(0xffffffffu, ls0, 1);
        ls0 += __shfl_xor_sync(0xffffffffu, ls0, 2);
        ls1 += __shfl_xor_sync(0xffffffffu, ls1, 1);
        ls1 += __shfl_xor_sync(0xffffffffu, ls1, 2);
        l0 = l0 * corr0 + ls0;
        l1 = l1 * corr1 + ls1;

#pragma unroll
        for (int nc = 0; nc < 8; ++nc) {
            oacc[nc][0] *= corr0; oacc[nc][1] *= corr0;
            oacc[nc][2] *= corr1; oacc[nc][3] *= corr1;
        }

#pragma unroll
        for (int kk = 0; kk < 4; ++kk) {
            uint32_t pa[4];
            pa[0] = packh2(sacc[2 * kk][0],     sacc[2 * kk][1]);
            pa[1] = packh2(sacc[2 * kk][2],     sacc[2 * kk][3]);
            pa[2] = packh2(sacc[2 * kk + 1][0], sacc[2 * kk + 1][1]);
            pa[3] = packh2(sacc[2 * kk + 1][2], sacc[2 * kk + 1][3]);
#pragma unroll
            for (int nc = 0; nc < 8; nc += 2) {
                uint32_t vb[4];
                LDMATRIX_X4_T(vb, vOff + (uint32_t)((kk * 16 * ATT_LDH + nc * 8) * 2));
                MMA16816(oacc[nc],     pa, vb);
                MMA16816(oacc[nc + 1], pa, vb + 2);
            }
        }

        buf = (buf == 2) ? 0 : buf + 1;
        nb  = (nb  == 2) ? 0 : nb  + 1;
        // no trailing sync: next iteration's barrier protects buffer reuse
    }

    const int qrow0 = q0 + wid * 16 + gid;
    const float fin0 = (qrow0     < len) ? (1.0f / l0) : 0.f;
    const float fin1 = (qrow0 + 8 < len) ? (1.0f / l1) : 0.f;
    __half* base0 = ctxh + ((size_t)bb * SS + qrow0) * EE + hh * DD;
    __half* base1 = base0 + (size_t)8 * EE;
#pragma unroll
    for (int nc = 0; nc < 8; ++nc) {
        const int d = nc * 8 + t4 * 2;
        *(__half2*)(base0 + d) = __floats2half2_rn(oacc[nc][0] * fin0, oacc[nc][1] * fin0);
        *(__half2*)(base1 + d) = __floats2half2_rn(oacc[nc][2] * fin1, oacc[nc][3] * fin1);
    }
}

// ---------------------------------------------------------------------------
// Launch
// ---------------------------------------------------------------------------
extern "C" void kernel_launch(void* const* d_in, const int* in_sizes, int n_in,
                              void* d_out, int out_size)
{
    const float* x            = (const float*)d_in[0];
    const unsigned char* mask = (const unsigned char*)d_in[1];
    const float* Wqkv_w       = (const float*)d_in[2];
    const float* Wqkv_b       = (const float*)d_in[3];
    const float* out_w        = (const float*)d_in[4];
    const float* out_b        = (const float*)d_in[5];
    float* out                = (float*)d_out;

    __half *xh, *wqkvh, *owh, *qh, *kh, *vh, *ctxh;
    cudaGetSymbolAddress((void**)&xh,    g_xh);
    cudaGetSymbolAddress((void**)&wqkvh, g_wqkvh);
    cudaGetSymbolAddress((void**)&owh,   g_owh);
    cudaGetSymbolAddress((void**)&qh,    g_qh);
    cudaGetSymbolAddress((void**)&kh,    g_kh);
    cudaGetSymbolAddress((void**)&vh,    g_vh);
    cudaGetSymbolAddress((void**)&ctxh,  g_ctxh);

    // 1) lengths + fused fp16 conversion (one launch)
    lengths_kernel<<<BB, 32>>>(mask);
    conv_all<<<(CN1 + CN2 + CN3 + 255) / 256, 256>>>(x, Wqkv_w, out_w);

    // 2) QKV projection (3-stage ring mma.sync GEMM + padded-slab skip)
    cudaFuncSetAttribute(tc_gemm<0>, cudaFuncAttributeMaxDynamicSharedMemorySize, GEMM_SMEM_BYTES);
    cudaFuncSetAttribute(tc_gemm<1>, cudaFuncAttributeMaxDynamicSharedMemorySize, GEMM_SMEM_BYTES);
    {
        dim3 grid(3 * EE / BN, (BB * SS) / BM);
        tc_gemm<0><<<grid, 256, GEMM_SMEM_BYTES>>>(xh, wqkvh, Wqkv_b, nullptr, qh, kh, vh);
    }

    // 3) flash attention (3-stage ring, hoisted addresses) -> ctx fp16
    cudaFuncSetAttribute(attn_kernel, cudaFuncAttributeMaxDynamicSharedMemorySize, ATT_SMEM_BYTES);
    attn_kernel<<<dim3(SS / 128, HH, BB), 256, ATT_SMEM_BYTES>>>(qh, kh, vh, ctxh);

    // 4) output projection (3-stage ring + bias-fill for padded slabs)
    {
        dim3 grid(EE / BN, (BB * SS) / BM);
        tc_gemm<1><<<grid, 256, GEMM_SMEM_BYTES>>>(ctxh, owh, out_b, out, nullptr, nullptr, nullptr);
    }
}

// round 13
// speedup vs baseline: 1.0014x; 1.0002x over previous
#include <cuda_runtime.h>
#include <cuda_fp16.h>
#include <math.h>
#include <stdint.h>

// Problem constants
#define BB 8
#define SS 1024
#define EE 768
#define HH 12
#define DD 64

// GEMM tiling
#define BM 128
#define BN 128
#define BK 64
#define LDH 72            // padded halves stride in smem tiles

// Attention smem stride (halves)
#define ATT_LDH 72

// q pre-scale: 1/sqrt(64) * log2(e)  (softmax runs in exp2 domain)
#define QSCALE (0.125f * 1.4426950408889634f)

// Scratch (allocation-free rule: __device__ globals)
__device__ __half g_xh[(size_t)BB * SS * EE];
__device__ __half g_wqkvh[(size_t)3 * EE * EE];
__device__ __half g_owh[(size_t)EE * EE];
__device__ __half g_qh[(size_t)BB * HH * SS * DD];
__device__ __half g_kh[(size_t)BB * HH * SS * DD];
__device__ __half g_vh[(size_t)BB * HH * SS * DD];
__device__ __half g_ctxh[(size_t)BB * SS * EE];
__device__ int    g_len[BB];

__device__ __forceinline__ uint32_t packh2(float a, float b) {
    __half2 h = __floats2half2_rn(a, b);
    return *(uint32_t*)&h;
}

#define MMA16816(C, A, B)                                                      \
    asm volatile("mma.sync.aligned.m16n8k16.row.col.f32.f16.f16.f32 "          \
        "{%0,%1,%2,%3}, {%4,%5,%6,%7}, {%8,%9}, {%0,%1,%2,%3};"                \
        : "+f"((C)[0]), "+f"((C)[1]), "+f"((C)[2]), "+f"((C)[3])               \
        : "r"((A)[0]), "r"((A)[1]), "r"((A)[2]), "r"((A)[3]),                  \
          "r"((B)[0]), "r"((B)[1]))

#define LDMATRIX_X4(R, ADDR)                                                   \
    asm volatile("ldmatrix.sync.aligned.m8n8.x4.shared.b16 {%0,%1,%2,%3}, [%4];" \
        : "=r"((R)[0]), "=r"((R)[1]), "=r"((R)[2]), "=r"((R)[3]) : "r"(ADDR))

#define LDMATRIX_X4_T(R, ADDR)                                                 \
    asm volatile("ldmatrix.sync.aligned.m8n8.x4.trans.shared.b16 {%0,%1,%2,%3}, [%4];" \
        : "=r"((R)[0]), "=r"((R)[1]), "=r"((R)[2]), "=r"((R)[3]) : "r"(ADDR))

// ---------------------------------------------------------------------------
// Fused fp32 -> fp16 conversion for x, Wqkv_w, out_w (one launch)
// ---------------------------------------------------------------------------
#define CN1 (BB * SS * EE / 4)
#define CN2 (3 * EE * EE / 4)
#define CN3 (EE * EE / 4)

__global__ void conv_all(const float* __restrict__ x, const float* __restrict__ w1,
                         const float* __restrict__ w2)
{
    int i = blockIdx.x * 256 + threadIdx.x;
    const float* src;
    __half* dst;
    if (i < CN1)              { src = x;  dst = g_xh; }
    else if (i < CN1 + CN2)   { src = w1; dst = g_wqkvh; i -= CN1; }
    else if (i < CN1+CN2+CN3) { src = w2; dst = g_owh;   i -= CN1 + CN2; }
    else return;
    const float4 v = ((const float4*)src)[i];
    ((__half2*)dst)[i * 2]     = __floats2half2_rn(v.x, v.y);
    ((__half2*)dst)[i * 2 + 1] = __floats2half2_rn(v.z, v.w);
}

// ---------------------------------------------------------------------------
// Mask -> per-batch valid length (prefix mask; count nonzeros).
// ---------------------------------------------------------------------------
__global__ void lengths_kernel(const unsigned char* __restrict__ mask)
{
    const int b = blockIdx.x;
    const int lane = threadIdx.x;
    int cnt = 0;
    if (mask[1] != 0) {
        const unsigned char* row = mask + (size_t)b * SS;
        for (int i = lane; i < SS; i += 32) cnt += (row[i] != 0);
    } else {
        const unsigned int* row = (const unsigned int*)mask + (size_t)b * SS;
        for (int i = lane; i < SS; i += 32) cnt += (row[i] != 0u);
    }
#pragma unroll
    for (int o = 16; o; o >>= 1) cnt += __shfl_xor_sync(0xffffffffu, cnt, o);
    if (lane == 0) g_len[b] = cnt;
}

// ---------------------------------------------------------------------------
// fp16 GEMM via raw mma.sync + ldmatrix.
// 3-stage cp.async ring, ONE __syncthreads per k-iteration, hoisted
// ldmatrix base addresses. CTA 128x128, BK=64, 8 warps (4m x 2n).
// MODE 0: scatter q/k/v fp16 (q scaled by QSCALE). MODE 1: fp32 C.
// ---------------------------------------------------------------------------
#define GEMM_BUF_HALVES (2 * BM * LDH)                    // A+B per stage
#define GEMM_SMEM_BYTES (3 * GEMM_BUF_HALVES * 2)         // 108 KB

template <int MODE>
__global__ __launch_bounds__(256, 2)
void tc_gemm(const __half* __restrict__ A, const __half* __restrict__ W,
             const float* __restrict__ bias, float* __restrict__ C,
             __half* __restrict__ Qo, __half* __restrict__ Ko, __half* __restrict__ Vo)
{
    extern __shared__ char smraw[];
    __half* sbuf = (__half*)smraw;

    const int tid    = threadIdx.x;
    const int wid    = tid >> 5;
    const int lane   = tid & 31;
    const int warp_m = wid & 3;
    const int warp_n = wid >> 2;
    const int m0     = blockIdx.y * BM;
    const int n0     = blockIdx.x * BN;

    const int len = g_len[m0 >> 10];
    if ((m0 & 1023) >= len) {
        if (MODE == 0) return;
        for (int idx = tid; idx < BM * (EE / 4); idx += 256) {
            const int row = idx / (EE / 4);
            const int c4  = idx % (EE / 4);
            *(float4*)(C + (size_t)(m0 + row) * EE + c4 * 4) =
                *(const float4*)(bias + c4 * 4);
        }
        return;
    }

    const __half* Abase = A + (size_t)m0 * EE;
    const __half* Wbase = W + (size_t)n0 * EE;

    float acc[2][8][4];
#pragma unroll
    for (int i = 0; i < 2; ++i)
#pragma unroll
        for (int j = 0; j < 8; ++j)
#pragma unroll
            for (int r = 0; r < 4; ++r) acc[i][j][r] = 0.f;

    auto issue_tile = [&](int t, int buf) {
        const __half* Ag = Abase + t * BK;
        const __half* Wg = Wbase + t * BK;
        __half* sA = sbuf + buf * GEMM_BUF_HALVES;
        __half* sB = sA + BM * LDH;
#pragma unroll
        for (int i = 0; i < 4; ++i) {
            const int idx = tid + (i << 8);
            const int row = idx >> 3;
            const int seg = idx & 7;
            const __half* srcA = Ag + (size_t)row * EE + seg * 8;
            const __half* srcB = Wg + (size_t)row * EE + seg * 8;
            uint32_t dA = (uint32_t)__cvta_generic_to_shared(sA + row * LDH + seg * 8);
            uint32_t dB = (uint32_t)__cvta_generic_to_shared(sB + row * LDH + seg * 8);
            asm volatile("cp.async.cg.shared.global [%0], [%1], 16;" :: "r"(dA), "l"(srcA));
            asm volatile("cp.async.cg.shared.global [%0], [%1], 16;" :: "r"(dB), "l"(srcB));
        }
        asm volatile("cp.async.commit_group;" ::: "memory");
    };

    // hoisted ldmatrix lane bases (byte addresses in shared window)
    const int ar  = lane & 15;
    const int ac8 = (lane >> 4) * 8;
    const int br  = ((lane >> 4) & 1) * 8 + (lane & 7);
    const int bc8 = ((lane >> 3) & 1) * 8;
    const uint32_t sb0   = (uint32_t)__cvta_generic_to_shared(sbuf);
    const uint32_t aBase = sb0 + (uint32_t)(((warp_m * 32 + ar) * LDH + ac8) * 2);
    const uint32_t bBase = sb0 + (uint32_t)(BM * LDH * 2)
                               + (uint32_t)(((warp_n * 64 + br) * LDH + bc8) * 2);

    const int nT = EE / BK;    // 12
    issue_tile(0, 0);
    issue_tile(1, 1);

    int buf = 0, nb = 2;
    for (int t = 0; t < nT; ++t) {
        asm volatile("cp.async.wait_group 1;" ::: "memory");
        __syncthreads();   // buffer `buf` ready; all warps done with buf(t-1)

        if (t + 2 < nT) issue_tile(t + 2, nb);
        else            asm volatile("cp.async.commit_group;" ::: "memory");

        const uint32_t bufOff = (uint32_t)buf * (GEMM_BUF_HALVES * 2);
        const uint32_t aOff = aBase + bufOff;
        const uint32_t bOff = bBase + bufOff;
#pragma unroll
        for (int kk = 0; kk < BK / 16; ++kk) {
            uint32_t af[2][4];
#pragma unroll
            for (int i = 0; i < 2; ++i)
                LDMATRIX_X4(af[i], aOff + (uint32_t)((i * 16 * LDH + kk * 16) * 2));
#pragma unroll
            for (int jc = 0; jc < 8; jc += 2) {
                uint32_t kb[4];
                LDMATRIX_X4(kb, bOff + (uint32_t)((jc * 8 * LDH + kk * 16) * 2));
#pragma unroll
                for (int i = 0; i < 2; ++i) {
                    MMA16816(acc[i][jc],     af[i], kb);
                    MMA16816(acc[i][jc + 1], af[i], kb + 2);
                }
            }
        }
        buf = (buf == 2) ? 0 : buf + 1;
        nb  = (nb  == 2) ? 0 : nb  + 1;
        // no trailing sync: next iteration's barrier protects buffer reuse
    }

    const int gid = lane >> 2;
    const int t4  = lane & 3;
#pragma unroll
    for (int i = 0; i < 2; ++i) {
        const int mrow = m0 + warp_m * 32 + i * 16 + gid;
#pragma unroll
        for (int jc = 0; jc < 8; ++jc) {
            const int n = n0 + warp_n * 64 + jc * 8 + t4 * 2;
            const float2 bv = *(const float2*)(bias + n);
            float ox0 = acc[i][jc][0] + bv.x, oy0 = acc[i][jc][1] + bv.y;
            float ox1 = acc[i][jc][2] + bv.x, oy1 = acc[i][jc][3] + bv.y;
            if (MODE == 0) {
                const int c  = n / EE;
                const int rr = n - c * EE;
                const int h  = rr >> 6;
                const int d  = rr & 63;
                if (c == 0) { ox0 *= QSCALE; oy0 *= QSCALE; ox1 *= QSCALE; oy1 *= QSCALE; }
                __half* dst = ((c == 0) ? Qo : (c == 1) ? Ko : Vo);
                const int b = mrow >> 10;
                const int s = mrow & 1023;
                __half* p0 = dst + ((((size_t)b * HH + h) * SS + s) * DD + d);
                *(__half2*)p0                      = __floats2half2_rn(ox0, oy0);
                *(__half2*)(p0 + (size_t)8 * DD)   = __floats2half2_rn(ox1, oy1);
            } else {
                *(float2*)(C + (size_t)mrow * EE + n)       = make_float2(ox0, oy0);
                *(float2*)(C + (size_t)(mrow + 8) * EE + n) = make_float2(ox1, oy1);
            }
        }
    }
}

// ---------------------------------------------------------------------------
// Flash attention v6: register-resident FA2, exp2 softmax, 3-stage K/V ring,
// one __syncthreads per tile, hoisted ldmatrix bases, 2 CTAs/SM.
// smem: sQ 128x72 | sK 3x(64x72) | sV 3x(64x72) = 72 KB
// ---------------------------------------------------------------------------
#define ATT_KV_HALVES (64 * ATT_LDH)
#define ATT_SMEM_BYTES ((128 * ATT_LDH + 6 * ATT_KV_HALVES) * 2)

__global__ __launch_bounds__(256, 2)
void attn_kernel(const __half* __restrict__ qh, const __half* __restrict__ kh,
                 const __half* __restrict__ vh, __half* __restrict__ ctxh)
{
    extern __shared__ char smraw[];
    __half* sQ  = (__half*)smraw;                        // 128 x 72
    __half* sK0 = sQ + 128 * ATT_LDH;                    // 3 x (64 x 72)
    __half* sV0 = sK0 + 3 * ATT_KV_HALVES;               // 3 x (64 x 72)

    const int tid  = threadIdx.x;
    const int wid  = tid >> 5;
    const int lane = tid & 31;
    const int gid  = lane >> 2;
    const int t4   = lane & 3;
    const int hh   = blockIdx.y;
    const int bb   = blockIdx.z;
    const int bh   = bb * HH + hh;
    const int q0   = blockIdx.x * 128;
    const int len  = g_len[bb];

    if (q0 >= len) return;   // gemm1's bias-fill never reads these ctx rows

    const uint4* kg = (const uint4*)(kh + (size_t)bh * SS * DD);
    const uint4* vg = (const uint4*)(vh + (size_t)bh * SS * DD);

    auto issue_kv = [&](int j0, int buf) {
        __half* dK = sK0 + buf * ATT_KV_HALVES;
        __half* dV = sV0 + buf * ATT_KV_HALVES;
#pragma unroll
        for (int i = 0; i < 2; ++i) {
            const int idx = tid + (i << 8);
            const int r = idx >> 3, seg = idx & 7;
            const uint4* sk = &kg[(j0 + r) * 8 + seg];
            const uint4* sv = &vg[(j0 + r) * 8 + seg];
            uint32_t aK = (uint32_t)__cvta_generic_to_shared(dK + r * ATT_LDH + seg * 8);
            uint32_t aV = (uint32_t)__cvta_generic_to_shared(dV + r * ATT_LDH + seg * 8);
            asm volatile("cp.async.cg.shared.global [%0], [%1], 16;" :: "r"(aK), "l"(sk));
            asm volatile("cp.async.cg.shared.global [%0], [%1], 16;" :: "r"(aV), "l"(sv));
        }
        asm volatile("cp.async.commit_group;" ::: "memory");
    };

    const int nTiles = (len + 63) >> 6;

    issue_kv(0, 0);
    if (nTiles > 1) issue_kv(64, 1);
    else            asm volatile("cp.async.commit_group;" ::: "memory");

    // stage Q while tile 0 is in flight
    {
        const uint4* qg = (const uint4*)(qh + ((size_t)bh * SS + q0) * DD);
#pragma unroll
        for (int i = 0; i < 4; ++i) {
            const int idx = tid + (i << 8);
            const int r = idx >> 3, seg = idx & 7;
            *(uint4*)(sQ + r * ATT_LDH + seg * 8) = qg[r * 8 + seg];
        }
    }
    __syncthreads();

    uint32_t qa[4][4];
    {
        const int r  = wid * 16 + (lane & 15);
        const int c8 = (lane >> 4) * 8;
#pragma unroll
        for (int kk = 0; kk < 4; ++kk) {
            uint32_t a = (uint32_t)__cvta_generic_to_shared(sQ + r * ATT_LDH + kk * 16 + c8);
            LDMATRIX_X4(qa[kk], a);
        }
    }

    // hoisted K/V ldmatrix lane bases
    const int krb = ((lane >> 4) & 1) * 8 + (lane & 7);
    const int kcb = ((lane >> 3) & 1) * 8;
    const int vrb = ((lane >> 3) & 1) * 8 + (lane & 7);
    const int vcb = (lane >> 4) * 8;
    const uint32_t kBase = (uint32_t)__cvta_generic_to_shared(sK0)
                         + (uint32_t)((krb * ATT_LDH + kcb) * 2);
    const uint32_t vBase = (uint32_t)__cvta_generic_to_shared(sV0)
                         + (uint32_t)((vrb * ATT_LDH + vcb) * 2);

    float oacc[8][4];
#pragma unroll
    for (int i = 0; i < 8; ++i)
#pragma unroll
        for (int j = 0; j < 4; ++j) oacc[i][j] = 0.f;
    float m0r = -1e30f, m1r = -1e30f, l0 = 0.f, l1 = 0.f;

    int buf = 0, nb = 2;
    for (int t = 0; t < nTiles; ++t) {
        const int j0 = t << 6;

        asm volatile("cp.async.wait_group 1;" ::: "memory");
        __syncthreads();   // buffer `buf` filled & visible; all warps past t-1

        if (t + 2 < nTiles) issue_kv(j0 + 128, nb);
        else                asm volatile("cp.async.commit_group;" ::: "memory");

        const uint32_t kvOff = (uint32_t)buf * (ATT_KV_HALVES * 2);
        const uint32_t kOff = kBase + kvOff;
        const uint32_t vOff = vBase + kvOff;

        float sacc[8][4];
#pragma unroll
        for (int i = 0; i < 8; ++i)
#pragma unroll
            for (int j = 0; j < 4; ++j) sacc[i][j] = 0.f;

#pragma unroll
        for (int kk = 0; kk < 4; ++kk) {
#pragma unroll
            for (int jc = 0; jc < 8; jc += 2) {
                uint32_t kb[4];
                LDMATRIX_X4(kb, kOff + (uint32_t)((jc * 8 * ATT_LDH + kk * 16) * 2));
                MMA16816(sacc[jc],     qa[kk], kb);
                MMA16816(sacc[jc + 1], qa[kk], kb + 2);
            }
        }

        const int nk = min(64, len - j0);
        if (nk < 64) {
#pragma unroll
            for (int jc = 0; jc < 8; ++jc) {
                const int c = jc * 8 + t4 * 2;
                if (c     >= nk) { sacc[jc][0] = -1e30f; sacc[jc][2] = -1e30f; }
                if (c + 1 >= nk) { sacc[jc][1] = -1e30f; sacc[jc][3] = -1e30f; }
            }
        }
        float mt0 = -1e30f, mt1 = -1e30f;
#pragma unroll
        for (int jc = 0; jc < 8; ++jc) {
            mt0 = fmaxf(mt0, fmaxf(sacc[jc][0], sacc[jc][1]));
            mt1 = fmaxf(mt1, fmaxf(sacc[jc][2], sacc[jc][3]));
        }
        mt0 = fmaxf(mt0, __shfl_xor_sync(0xffffffffu, mt0, 1));
        mt0 = fmaxf(mt0, __shfl_xor_sync(0xffffffffu, mt0, 2));
        mt1 = fmaxf(mt1, __shfl_xor_sync(0xffffffffu, mt1, 1));
        mt1 = fmaxf(mt1, __shfl_xor_sync(0xffffffffu, mt1, 2));

        const float mn0 = fmaxf(m0r, mt0), mn1 = fmaxf(m1r, mt1);
        const float corr0 = exp2f(m0r - mn0), corr1 = exp2f(m1r - mn1);
        m0r = mn0; m1r = mn1;

        float ls0 = 0.f, ls1 = 0.f;
#pragma unroll
        for (int jc = 0; jc < 8; ++jc) {
            sacc[jc][0] = exp2f(sacc[jc][0] - mn0);
            sacc[jc][1] = exp2f(sacc[jc][1] - mn0);
            sacc[jc][2] = exp2f(sacc[jc][2] - mn1);
            sacc[jc][3] = exp2f(sacc[jc][3] - mn1);
            ls0 += sacc[jc][0] + sacc[jc][1];
            ls1 += sacc[jc][2] + sacc[jc][3];
        }
        ls0 += __shfl_xor_sync(0xffffffffu, ls0, 1);
        ls0 += __shfl_xor_sync(0xffffffffu, ls0, 2);
        ls1 += __shfl_xor_sync(0xffffffffu, ls1, 1);
        ls1 += __shfl_xor_sync(0xffffffffu, ls1, 2);
        l0 = l0 * corr0 + ls0;
        l1 = l1 * corr1 + ls1;

#pragma unroll
        for (int nc = 0; nc < 8; ++nc) {
            oacc[nc][0] *= corr0; oacc[nc][1] *= corr0;
            oacc[nc][2] *= corr1; oacc[nc][3] *= corr1;
        }

#pragma unroll
        for (int kk = 0; kk < 4; ++kk) {
            uint32_t pa[4];
            pa[0] = packh2(sacc[2 * kk][0],     sacc[2 * kk][1]);
            pa[1] = packh2(sacc[2 * kk][2],     sacc[2 * kk][3]);
            pa[2] = packh2(sacc[2 * kk + 1][0], sacc[2 * kk + 1][1]);
            pa[3] = packh2(sacc[2 * kk + 1][2], sacc[2 * kk + 1][3]);
#pragma unroll
            for (int nc = 0; nc < 8; nc += 2) {
                uint32_t vb[4];
                LDMATRIX_X4_T(vb, vOff + (uint32_t)((kk * 16 * ATT_LDH + nc * 8) * 2));
                MMA16816(oacc[nc],     pa, vb);
                MMA16816(oacc[nc + 1], pa, vb + 2);
            }
        }

        buf = (buf == 2) ? 0 : buf + 1;
        nb  = (nb  == 2) ? 0 : nb  + 1;
        // no trailing sync: next iteration's barrier protects buffer reuse
    }

    const int qrow0 = q0 + wid * 16 + gid;
    const float fin0 = (qrow0     < len) ? (1.0f / l0) : 0.f;
    const float fin1 = (qrow0 + 8 < len) ? (1.0f / l1) : 0.f;
    __half* base0 = ctxh + ((size_t)bb * SS + qrow0) * EE + hh * DD;
    __half* base1 = base0 + (size_t)8 * EE;
#pragma unroll
    for (int nc = 0; nc < 8; ++nc) {
        const int d = nc * 8 + t4 * 2;
        *(__half2*)(base0 + d) = __floats2half2_rn(oacc[nc][0] * fin0, oacc[nc][1] * fin0);
        *(__half2*)(base1 + d) = __floats2half2_rn(oacc[nc][2] * fin1, oacc[nc][3] * fin1);
    }
}

// ---------------------------------------------------------------------------
// Launch
// ---------------------------------------------------------------------------
extern "C" void kernel_launch(void* const* d_in, const int* in_sizes, int n_in,
                              void* d_out, int out_size)
{
    const float* x            = (const float*)d_in[0];
    const unsigned char* mask = (const unsigned char*)d_in[1];
    const float* Wqkv_w       = (const float*)d_in[2];
    const float* Wqkv_b       = (const float*)d_in[3];
    const float* out_w        = (const float*)d_in[4];
    const float* out_b        = (const float*)d_in[5];
    float* out                = (float*)d_out;

    __half *xh, *wqkvh, *owh, *qh, *kh, *vh, *ctxh;
    cudaGetSymbolAddress((void**)&xh,    g_xh);
    cudaGetSymbolAddress((void**)&wqkvh, g_wqkvh);
    cudaGetSymbolAddress((void**)&owh,   g_owh);
    cudaGetSymbolAddress((void**)&qh,    g_qh);
    cudaGetSymbolAddress((void**)&kh,    g_kh);
    cudaGetSymbolAddress((void**)&vh,    g_vh);
    cudaGetSymbolAddress((void**)&ctxh,  g_ctxh);

    // 1) lengths + fused fp16 conversion (one launch)
    lengths_kernel<<<BB, 32>>>(mask);
    conv_all<<<(CN1 + CN2 + CN3 + 255) / 256, 256>>>(x, Wqkv_w, out_w);

    // 2) QKV projection (3-stage ring mma.sync GEMM + padded-slab skip)
    cudaFuncSetAttribute(tc_gemm<0>, cudaFuncAttributeMaxDynamicSharedMemorySize, GEMM_SMEM_BYTES);
    cudaFuncSetAttribute(tc_gemm<1>, cudaFuncAttributeMaxDynamicSharedMemorySize, GEMM_SMEM_BYTES);
    {
        dim3 grid(3 * EE / BN, (BB * SS) / BM);
        tc_gemm<0><<<grid, 256, GEMM_SMEM_BYTES>>>(xh, wqkvh, Wqkv_b, nullptr, qh, kh, vh);
    }

    // 3) flash attention (3-stage ring, hoisted addresses) -> ctx fp16
    cudaFuncSetAttribute(attn_kernel, cudaFuncAttributeMaxDynamicSharedMemorySize, ATT_SMEM_BYTES);
    attn_kernel<<<dim3(SS / 128, HH, BB), 256, ATT_SMEM_BYTES>>>(qh, kh, vh, ctxh);

    // 4) output projection (3-stage ring + bias-fill for padded slabs)
    {
        dim3 grid(EE / BN, (BB * SS) / BM);
        tc_gemm<1><<<grid, 256, GEMM_SMEM_BYTES>>>(ctxh, owh, out_b, out, nullptr, nullptr, nullptr);
    }
}

// round 14
// speedup vs baseline: 1.0522x; 1.0508x over previous
#include <cuda_runtime.h>
#include <cuda_fp16.h>
#include <math.h>
#include <stdint.h>

// Problem constants
#define BB 8
#define SS 1024
#define EE 768
#define HH 12
#define DD 64

// GEMM tiling
#define BM 128
#define BN 128
#define BK 64
#define LDH 72            // padded halves stride in smem tiles

// Attention smem stride (halves)
#define ATT_LDH 72

// q pre-scale: 1/sqrt(64) * log2(e)  (softmax runs in exp2 domain)
#define QSCALE (0.125f * 1.4426950408889634f)

// Scratch (allocation-free rule: __device__ globals)
__device__ __half g_xh[(size_t)BB * SS * EE];
__device__ __half g_wqkvh[(size_t)3 * EE * EE];
__device__ __half g_owh[(size_t)EE * EE];
__device__ __half g_qh[(size_t)BB * HH * SS * DD];
__device__ __half g_kh[(size_t)BB * HH * SS * DD];
__device__ __half g_vh[(size_t)BB * HH * SS * DD];
__device__ __half g_ctxh[(size_t)BB * SS * EE];
__device__ int    g_len[BB];

__device__ __forceinline__ uint32_t packh2(float a, float b) {
    __half2 h = __floats2half2_rn(a, b);
    return *(uint32_t*)&h;
}

#define MMA16816(C, A, B)                                                      \
    asm volatile("mma.sync.aligned.m16n8k16.row.col.f32.f16.f16.f32 "          \
        "{%0,%1,%2,%3}, {%4,%5,%6,%7}, {%8,%9}, {%0,%1,%2,%3};"                \
        : "+f"((C)[0]), "+f"((C)[1]), "+f"((C)[2]), "+f"((C)[3])               \
        : "r"((A)[0]), "r"((A)[1]), "r"((A)[2]), "r"((A)[3]),                  \
          "r"((B)[0]), "r"((B)[1]))

#define LDMATRIX_X4(R, ADDR)                                                   \
    asm volatile("ldmatrix.sync.aligned.m8n8.x4.shared.b16 {%0,%1,%2,%3}, [%4];" \
        : "=r"((R)[0]), "=r"((R)[1]), "=r"((R)[2]), "=r"((R)[3]) : "r"(ADDR))

#define LDMATRIX_X4_T(R, ADDR)                                                 \
    asm volatile("ldmatrix.sync.aligned.m8n8.x4.trans.shared.b16 {%0,%1,%2,%3}, [%4];" \
        : "=r"((R)[0]), "=r"((R)[1]), "=r"((R)[2]), "=r"((R)[3]) : "r"(ADDR))

#define EX2H2(D, S) \
    asm("ex2.approx.f16x2 %0, %1;" : "=r"(D) : "r"(S))

// ---------------------------------------------------------------------------
// Fused: per-batch lengths (block 0) + fp32->fp16 conversion of x, Wqkv_w,
// out_w. 4 independent chunks per thread (MLP=4).
// ---------------------------------------------------------------------------
#define CN1 (BB * SS * EE / 4)
#define CN2 (3 * EE * EE / 4)
#define CN3 (EE * EE / 4)
#define CTOT (CN1 + CN2 + CN3)

__global__ void conv_all(const float* __restrict__ x, const float* __restrict__ w1,
                         const float* __restrict__ w2, const unsigned char* __restrict__ mask)
{
    if (blockIdx.x == 0) {
        // 8 warps <-> 8 batches: count mask prefix length
        const int b    = threadIdx.x >> 5;
        const int lane = threadIdx.x & 31;
        int cnt = 0;
        if (mask[1] != 0) {
            const unsigned char* row = mask + (size_t)b * SS;
            for (int i = lane; i < SS; i += 32) cnt += (row[i] != 0);
        } else {
            const unsigned int* row = (const unsigned int*)mask + (size_t)b * SS;
            for (int i = lane; i < SS; i += 32) cnt += (row[i] != 0u);
        }
#pragma unroll
        for (int o = 16; o; o >>= 1) cnt += __shfl_xor_sync(0xffffffffu, cnt, o);
        if (lane == 0) g_len[b] = cnt;
    }

    const int base = blockIdx.x * 1024 + threadIdx.x;
#pragma unroll
    for (int u = 0; u < 4; ++u) {
        int i = base + u * 256;
        if (i < CTOT) {
            const float* src; __half* dst;
            if (i < CN1)            { src = x;  dst = g_xh; }
            else if (i < CN1 + CN2) { src = w1; dst = g_wqkvh; i -= CN1; }
            else                    { src = w2; dst = g_owh;   i -= CN1 + CN2; }
            const float4 v = ((const float4*)src)[i];
            ((__half2*)dst)[i * 2]     = __floats2half2_rn(v.x, v.y);
            ((__half2*)dst)[i * 2 + 1] = __floats2half2_rn(v.z, v.w);
        }
    }
}

// ---------------------------------------------------------------------------
// fp16 GEMM via raw mma.sync + ldmatrix (unchanged from R13 — known good).
// ---------------------------------------------------------------------------
#define GEMM_BUF_HALVES (2 * BM * LDH)
#define GEMM_SMEM_BYTES (3 * GEMM_BUF_HALVES * 2)

template <int MODE>
__global__ __launch_bounds__(256, 2)
void tc_gemm(const __half* __restrict__ A, const __half* __restrict__ W,
             const float* __restrict__ bias, float* __restrict__ C,
             __half* __restrict__ Qo, __half* __restrict__ Ko, __half* __restrict__ Vo)
{
    extern __shared__ char smraw[];
    __half* sbuf = (__half*)smraw;

    const int tid    = threadIdx.x;
    const int wid    = tid >> 5;
    const int lane   = tid & 31;
    const int warp_m = wid & 3;
    const int warp_n = wid >> 2;
    const int m0     = blockIdx.y * BM;
    const int n0     = blockIdx.x * BN;

    const int len = g_len[m0 >> 10];
    if ((m0 & 1023) >= len) {
        if (MODE == 0) return;
        for (int idx = tid; idx < BM * (EE / 4); idx += 256) {
            const int row = idx / (EE / 4);
            const int c4  = idx % (EE / 4);
            *(float4*)(C + (size_t)(m0 + row) * EE + c4 * 4) =
                *(const float4*)(bias + c4 * 4);
        }
        return;
    }

    const __half* Abase = A + (size_t)m0 * EE;
    const __half* Wbase = W + (size_t)n0 * EE;

    float acc[2][8][4];
#pragma unroll
    for (int i = 0; i < 2; ++i)
#pragma unroll
        for (int j = 0; j < 8; ++j)
#pragma unroll
            for (int r = 0; r < 4; ++r) acc[i][j][r] = 0.f;

    auto issue_tile = [&](int t, int buf) {
        const __half* Ag = Abase + t * BK;
        const __half* Wg = Wbase + t * BK;
        __half* sA = sbuf + buf * GEMM_BUF_HALVES;
        __half* sB = sA + BM * LDH;
#pragma unroll
        for (int i = 0; i < 4; ++i) {
            const int idx = tid + (i << 8);
            const int row = idx >> 3;
            const int seg = idx & 7;
            const __half* srcA = Ag + (size_t)row * EE + seg * 8;
            const __half* srcB = Wg + (size_t)row * EE + seg * 8;
            uint32_t dA = (uint32_t)__cvta_generic_to_shared(sA + row * LDH + seg * 8);
            uint32_t dB = (uint32_t)__cvta_generic_to_shared(sB + row * LDH + seg * 8);
            asm volatile("cp.async.cg.shared.global [%0], [%1], 16;" :: "r"(dA), "l"(srcA));
            asm volatile("cp.async.cg.shared.global [%0], [%1], 16;" :: "r"(dB), "l"(srcB));
        }
        asm volatile("cp.async.commit_group;" ::: "memory");
    };

    const int ar  = lane & 15;
    const int ac8 = (lane >> 4) * 8;
    const int br  = ((lane >> 4) & 1) * 8 + (lane & 7);
    const int bc8 = ((lane >> 3) & 1) * 8;
    const uint32_t sb0   = (uint32_t)__cvta_generic_to_shared(sbuf);
    const uint32_t aBase = sb0 + (uint32_t)(((warp_m * 32 + ar) * LDH + ac8) * 2);
    const uint32_t bBase = sb0 + (uint32_t)(BM * LDH * 2)
                               + (uint32_t)(((warp_n * 64 + br) * LDH + bc8) * 2);

    const int nT = EE / BK;    // 12
    issue_tile(0, 0);
    issue_tile(1, 1);

    int buf = 0, nb = 2;
    for (int t = 0; t < nT; ++t) {
        asm volatile("cp.async.wait_group 1;" ::: "memory");
        __syncthreads();

        if (t + 2 < nT) issue_tile(t + 2, nb);
        else            asm volatile("cp.async.commit_group;" ::: "memory");

        const uint32_t bufOff = (uint32_t)buf * (GEMM_BUF_HALVES * 2);
        const uint32_t aOff = aBase + bufOff;
        const uint32_t bOff = bBase + bufOff;
#pragma unroll
        for (int kk = 0; kk < BK / 16; ++kk) {
            uint32_t af[2][4];
#pragma unroll
            for (int i = 0; i < 2; ++i)
                LDMATRIX_X4(af[i], aOff + (uint32_t)((i * 16 * LDH + kk * 16) * 2));
#pragma unroll
            for (int jc = 0; jc < 8; jc += 2) {
                uint32_t kb[4];
                LDMATRIX_X4(kb, bOff + (uint32_t)((jc * 8 * LDH + kk * 16) * 2));
#pragma unroll
                for (int i = 0; i < 2; ++i) {
                    MMA16816(acc[i][jc],     af[i], kb);
                    MMA16816(acc[i][jc + 1], af[i], kb + 2);
                }
            }
        }
        buf = (buf == 2) ? 0 : buf + 1;
        nb  = (nb  == 2) ? 0 : nb  + 1;
    }

    const int gid = lane >> 2;
    const int t4  = lane & 3;
#pragma unroll
    for (int i = 0; i < 2; ++i) {
        const int mrow = m0 + warp_m * 32 + i * 16 + gid;
#pragma unroll
        for (int jc = 0; jc < 8; ++jc) {
            const int n = n0 + warp_n * 64 + jc * 8 + t4 * 2;
            const float2 bv = *(const float2*)(bias + n);
            float ox0 = acc[i][jc][0] + bv.x, oy0 = acc[i][jc][1] + bv.y;
            float ox1 = acc[i][jc][2] + bv.x, oy1 = acc[i][jc][3] + bv.y;
            if (MODE == 0) {
                const int c  = n / EE;
                const int rr = n - c * EE;
                const int h  = rr >> 6;
                const int d  = rr & 63;
                if (c == 0) { ox0 *= QSCALE; oy0 *= QSCALE; ox1 *= QSCALE; oy1 *= QSCALE; }
                __half* dst = ((c == 0) ? Qo : (c == 1) ? Ko : Vo);
                const int b = mrow >> 10;
                const int s = mrow & 1023;
                __half* p0 = dst + ((((size_t)b * HH + h) * SS + s) * DD + d);
                *(__half2*)p0                      = __floats2half2_rn(ox0, oy0);
                *(__half2*)(p0 + (size_t)8 * DD)   = __floats2half2_rn(ox1, oy1);
            } else {
                *(float2*)(C + (size_t)mrow * EE + n)       = make_float2(ox0, oy0);
                *(float2*)(C + (size_t)(mrow + 8) * EE + n) = make_float2(ox1, oy1);
            }
        }
    }
}

// ---------------------------------------------------------------------------
// Flash attention v7: register-resident FA2; P via ex2.approx.f16x2 (half the
// MUFU ops, pre-packed for PV); l via ones-vector MMA (no FADD chain/shfls);
// 3-stage K/V ring, one __syncthreads per tile, 2 CTAs/SM.
// ---------------------------------------------------------------------------
#define ATT_KV_HALVES (64 * ATT_LDH)
#define ATT_SMEM_BYTES ((128 * ATT_LDH + 6 * ATT_KV_HALVES) * 2)

__global__ __launch_bounds__(256, 2)
void attn_kernel(const __half* __restrict__ qh, const __half* __restrict__ kh,
                 const __half* __restrict__ vh, __half* __restrict__ ctxh)
{
    extern __shared__ char smraw[];
    __half* sQ  = (__half*)smraw;                        // 128 x 72
    __half* sK0 = sQ + 128 * ATT_LDH;                    // 3 x (64 x 72)
    __half* sV0 = sK0 + 3 * ATT_KV_HALVES;               // 3 x (64 x 72)

    const int tid  = threadIdx.x;
    const int wid  = tid >> 5;
    const int lane = tid & 31;
    const int gid  = lane >> 2;
    const int t4   = lane & 3;
    const int hh   = blockIdx.y;
    const int bb   = blockIdx.z;
    const int bh   = bb * HH + hh;
    const int q0   = blockIdx.x * 128;
    const int len  = g_len[bb];

    if (q0 >= len) return;   // gemm1's bias-fill never reads these ctx rows

    const uint4* kg = (const uint4*)(kh + (size_t)bh * SS * DD);
    const uint4* vg = (const uint4*)(vh + (size_t)bh * SS * DD);

    auto issue_kv = [&](int j0, int buf) {
        __half* dK = sK0 + buf * ATT_KV_HALVES;
        __half* dV = sV0 + buf * ATT_KV_HALVES;
#pragma unroll
        for (int i = 0; i < 2; ++i) {
            const int idx = tid + (i << 8);
            const int r = idx >> 3, seg = idx & 7;
            const uint4* sk = &kg[(j0 + r) * 8 + seg];
            const uint4* sv = &vg[(j0 + r) * 8 + seg];
            uint32_t aK = (uint32_t)__cvta_generic_to_shared(dK + r * ATT_LDH + seg * 8);
            uint32_t aV = (uint32_t)__cvta_generic_to_shared(dV + r * ATT_LDH + seg * 8);
            asm volatile("cp.async.cg.shared.global [%0], [%1], 16;" :: "r"(aK), "l"(sk));
            asm volatile("cp.async.cg.shared.global [%0], [%1], 16;" :: "r"(aV), "l"(sv));
        }
        asm volatile("cp.async.commit_group;" ::: "memory");
    };

    const int nTiles = (len + 63) >> 6;

    issue_kv(0, 0);
    if (nTiles > 1) issue_kv(64, 1);
    else            asm volatile("cp.async.commit_group;" ::: "memory");

    // stage Q while tile 0 is in flight
    {
        const uint4* qg = (const uint4*)(qh + ((size_t)bh * SS + q0) * DD);
#pragma unroll
        for (int i = 0; i < 4; ++i) {
            const int idx = tid + (i << 8);
            const int r = idx >> 3, seg = idx & 7;
            *(uint4*)(sQ + r * ATT_LDH + seg * 8) = qg[r * 8 + seg];
        }
    }
    __syncthreads();

    uint32_t qa[4][4];
    {
        const int r  = wid * 16 + (lane & 15);
        const int c8 = (lane >> 4) * 8;
#pragma unroll
        for (int kk = 0; kk < 4; ++kk) {
            uint32_t a = (uint32_t)__cvta_generic_to_shared(sQ + r * ATT_LDH + kk * 16 + c8);
            LDMATRIX_X4(qa[kk], a);
        }
    }

    const int krb = ((lane >> 4) & 1) * 8 + (lane & 7);
    const int kcb = ((lane >> 3) & 1) * 8;
    const int vrb = ((lane >> 3) & 1) * 8 + (lane & 7);
    const int vcb = (lane >> 4) * 8;
    const uint32_t kBase = (uint32_t)__cvta_generic_to_shared(sK0)
                         + (uint32_t)((krb * ATT_LDH + kcb) * 2);
    const uint32_t vBase = (uint32_t)__cvta_generic_to_shared(sV0)
                         + (uint32_t)((vrb * ATT_LDH + vcb) * 2);

    float oacc[8][4];
#pragma unroll
    for (int i = 0; i < 8; ++i)
#pragma unroll
        for (int j = 0; j < 4; ++j) oacc[i][j] = 0.f;
    float lacc[4] = {0.f, 0.f, 0.f, 0.f};   // row sums of P via ones-MMA
    float m0r = -1e30f, m1r = -1e30f;

    const uint32_t onesb[2] = {0x3C003C00u, 0x3C003C00u};  // fp16 1.0 x4

    int buf = 0, nb = 2;
    for (int t = 0; t < nTiles; ++t) {
        const int j0 = t << 6;

        asm volatile("cp.async.wait_group 1;" ::: "memory");
        __syncthreads();

        if (t + 2 < nTiles) issue_kv(j0 + 128, nb);
        else                asm volatile("cp.async.commit_group;" ::: "memory");

        const uint32_t kvOff = (uint32_t)buf * (ATT_KV_HALVES * 2);
        const uint32_t kOff = kBase + kvOff;
        const uint32_t vOff = vBase + kvOff;

        float sacc[8][4];
#pragma unroll
        for (int i = 0; i < 8; ++i)
#pragma unroll
            for (int j = 0; j < 4; ++j) sacc[i][j] = 0.f;

#pragma unroll
        for (int kk = 0; kk < 4; ++kk) {
#pragma unroll
            for (int jc = 0; jc < 8; jc += 2) {
                uint32_t kb[4];
                LDMATRIX_X4(kb, kOff + (uint32_t)((jc * 8 * ATT_LDH + kk * 16) * 2));
                MMA16816(sacc[jc],     qa[kk], kb);
                MMA16816(sacc[jc + 1], qa[kk], kb + 2);
            }
        }

        const int nk = min(64, len - j0);
        if (nk < 64) {
#pragma unroll
            for (int jc = 0; jc < 8; ++jc) {
                const int c = jc * 8 + t4 * 2;
                if (c     >= nk) { sacc[jc][0] = -1e30f; sacc[jc][2] = -1e30f; }
                if (c + 1 >= nk) { sacc[jc][1] = -1e30f; sacc[jc][3] = -1e30f; }
            }
        }
        float mt0 = -1e30f, mt1 = -1e30f;
#pragma unroll
        for (int jc = 0; jc < 8; ++jc) {
            mt0 = fmaxf(mt0, fmaxf(sacc[jc][0], sacc[jc][1]));
            mt1 = fmaxf(mt1, fmaxf(sacc[jc][2], sacc[jc][3]));
        }
        mt0 = fmaxf(mt0, __shfl_xor_sync(0xffffffffu, mt0, 1));
        mt0 = fmaxf(mt0, __shfl_xor_sync(0xffffffffu, mt0, 2));
        mt1 = fmaxf(mt1, __shfl_xor_sync(0xffffffffu, mt1, 1));
        mt1 = fmaxf(mt1, __shfl_xor_sync(0xffffffffu, mt1, 2));

        const float mn0 = fmaxf(m0r, mt0), mn1 = fmaxf(m1r, mt1);
        const float corr0 = exp2f(m0r - mn0), corr1 = exp2f(m1r - mn1);
        m0r = mn0; m1r = mn1;

        // P = exp2(s - m) directly in fp16 pairs (masked lanes: -inf -> 0)
        uint32_t ph[8][2];
#pragma unroll
        for (int jc = 0; jc < 8; ++jc) {
            const uint32_t d01 = packh2(sacc[jc][0] - mn0, sacc[jc][1] - mn0);
            const uint32_t d23 = packh2(sacc[jc][2] - mn1, sacc[jc][3] - mn1);
            EX2H2(ph[jc][0], d01);
            EX2H2(ph[jc][1], d23);
        }

        // rescale running accumulators
        lacc[0] *= corr0; lacc[1] *= corr0;
        lacc[2] *= corr1; lacc[3] *= corr1;
#pragma unroll
        for (int nc = 0; nc < 8; ++nc) {
            oacc[nc][0] *= corr0; oacc[nc][1] *= corr0;
            oacc[nc][2] *= corr1; oacc[nc][3] *= corr1;
        }

        // O += P @ V ; lacc += P @ ones (row sums, no shuffles needed)
#pragma unroll
        for (int kk = 0; kk < 4; ++kk) {
            uint32_t pa[4];
            pa[0] = ph[2 * kk][0];
            pa[1] = ph[2 * kk][1];
            pa[2] = ph[2 * kk + 1][0];
            pa[3] = ph[2 * kk + 1][1];
            MMA16816(lacc, pa, onesb);
#pragma unroll
            for (int nc = 0; nc < 8; nc += 2) {
                uint32_t vb[4];
                LDMATRIX_X4_T(vb, vOff + (uint32_t)((kk * 16 * ATT_LDH + nc * 8) * 2));
                MMA16816(oacc[nc],     pa, vb);
                MMA16816(oacc[nc + 1], pa, vb + 2);
            }
        }

        buf = (buf == 2) ? 0 : buf + 1;
        nb  = (nb  == 2) ? 0 : nb  + 1;
    }

    const int qrow0 = q0 + wid * 16 + gid;
    const float fin0 = (qrow0     < len) ? (1.0f / lacc[0]) : 0.f;
    const float fin1 = (qrow0 + 8 < len) ? (1.0f / lacc[2]) : 0.f;
    __half* base0 = ctxh + ((size_t)bb * SS + qrow0) * EE + hh * DD;
    __half* base1 = base0 + (size_t)8 * EE;
#pragma unroll
    for (int nc = 0; nc < 8; ++nc) {
        const int d = nc * 8 + t4 * 2;
        *(__half2*)(base0 + d) = __floats2half2_rn(oacc[nc][0] * fin0, oacc[nc][1] * fin0);
        *(__half2*)(base1 + d) = __floats2half2_rn(oacc[nc][2] * fin1, oacc[nc][3] * fin1);
    }
}

// ---------------------------------------------------------------------------
// Launch
// ---------------------------------------------------------------------------
extern "C" void kernel_launch(void* const* d_in, const int* in_sizes, int n_in,
                              void* d_out, int out_size)
{
    const float* x            = (const float*)d_in[0];
    const unsigned char* mask = (const unsigned char*)d_in[1];
    const float* Wqkv_w       = (const float*)d_in[2];
    const float* Wqkv_b       = (const float*)d_in[3];
    const float* out_w        = (const float*)d_in[4];
    const float* out_b        = (const float*)d_in[5];
    float* out                = (float*)d_out;

    __half *xh, *wqkvh, *owh, *qh, *kh, *vh, *ctxh;
    cudaGetSymbolAddress((void**)&xh,    g_xh);
    cudaGetSymbolAddress((void**)&wqkvh, g_wqkvh);
    cudaGetSymbolAddress((void**)&owh,   g_owh);
    cudaGetSymbolAddress((void**)&qh,    g_qh);
    cudaGetSymbolAddress((void**)&kh,    g_kh);
    cudaGetSymbolAddress((void**)&vh,    g_vh);
    cudaGetSymbolAddress((void**)&ctxh,  g_ctxh);

    // 1) fused lengths + fp16 conversion (one launch, MLP=4)
    conv_all<<<(CTOT + 1023) / 1024, 256>>>(x, Wqkv_w, out_w, mask);

    // 2) QKV projection (3-stage ring mma.sync GEMM + padded-slab skip)
    cudaFuncSetAttribute(tc_gemm<0>, cudaFuncAttributeMaxDynamicSharedMemorySize, GEMM_SMEM_BYTES);
    cudaFuncSetAttribute(tc_gemm<1>, cudaFuncAttributeMaxDynamicSharedMemorySize, GEMM_SMEM_BYTES);
    {
        dim3 grid(3 * EE / BN, (BB * SS) / BM);
        tc_gemm<0><<<grid, 256, GEMM_SMEM_BYTES>>>(xh, wqkvh, Wqkv_b, nullptr, qh, kh, vh);
    }

    // 3) flash attention (f16x2 exp softmax + ones-MMA row sums) -> ctx fp16
    cudaFuncSetAttribute(attn_kernel, cudaFuncAttributeMaxDynamicSharedMemorySize, ATT_SMEM_BYTES);
    attn_kernel<<<dim3(SS / 128, HH, BB), 256, ATT_SMEM_BYTES>>>(qh, kh, vh, ctxh);

    // 4) output projection (3-stage ring + bias-fill for padded slabs)
    {
        dim3 grid(EE / BN, (BB * SS) / BM);
        tc_gemm<1><<<grid, 256, GEMM_SMEM_BYTES>>>(ctxh, owh, out_b, out, nullptr, nullptr, nullptr);
    }
}